// round 9
// baseline (speedup 1.0000x reference)
#include <cuda_runtime.h>

// Batched Kalman filter: B=262144, N=8, M=4, fp32.
// Warp-autonomous: each warp owns 16 batches end-to-end (stage -> compute ->
// drain) with __syncwarp only; NO block-wide barriers. Within a warp,
// 2 threads per batch (lane&1 = s owns rows {s,s+2,s+4,s+6}).
// F,P,H staged via smem; Q,R,z,x loaded directly. HP = A^T symmetry used.
// Outputs flat: x_new[B,8], P_new[B,8,8], K[B,8,4].

constexpr int BT  = 262144;
constexpr int TPB = 128;         // 4 independent warps
constexpr int WG  = 16;          // batches per warp
constexpr int GB  = 64;          // batches per block
constexpr float EPS = 1e-6f;

constexpr int SF = 68;           // padded stride, 64-float mats
constexpr int SH = 36;           // 32-float mats
constexpr int SX = 12;           // 8-float out vec
constexpr int WSM = WG*SF*2 + WG*SH + WG*SX;   // 2944 floats per warp

template<int E, int S>
__device__ __forceinline__ void stage_in_w(float* smp, const float* __restrict__ gp,
                                           int wb0, int lane) {
    const float4* g4 = reinterpret_cast<const float4*>(gp + (size_t)wb0 * E);
    constexpr int T4 = WG * E / 4;
#pragma unroll
    for (int i = lane; i < T4; i += 32) {
        float4 v = g4[i];
        int e = i * 4;
        *reinterpret_cast<float4*>(smp + (e / E) * S + (e % E)) = v;
    }
}

template<int E, int S>
__device__ __forceinline__ void stage_out_w(float* __restrict__ gp, const float* smp,
                                            int wb0, int lane) {
    float4* g4 = reinterpret_cast<float4*>(gp + (size_t)wb0 * E);
    constexpr int T4 = WG * E / 4;
#pragma unroll
    for (int i = lane; i < T4; i += 32) {
        int e = i * 4;
        g4[i] = *reinterpret_cast<const float4*>(smp + (e / E) * S + (e % E));
    }
}

__device__ __forceinline__ void ld_row8(float* d, const float* s) {
    float4 a = *reinterpret_cast<const float4*>(s);
    float4 b = *reinterpret_cast<const float4*>(s + 4);
    d[0]=a.x; d[1]=a.y; d[2]=a.z; d[3]=a.w;
    d[4]=b.x; d[5]=b.y; d[6]=b.z; d[7]=b.w;
}
__device__ __forceinline__ void st_row8(float* d, const float* s) {
    *reinterpret_cast<float4*>(d)     = make_float4(s[0], s[1], s[2], s[3]);
    *reinterpret_cast<float4*>(d + 4) = make_float4(s[4], s[5], s[6], s[7]);
}

__global__ __launch_bounds__(TPB, 4) void kf_kernel(
    const float* __restrict__ gx, const float* __restrict__ gP,
    const float* __restrict__ gF, const float* __restrict__ gQ,
    const float* __restrict__ gz, const float* __restrict__ gH,
    const float* __restrict__ gR, float* __restrict__ out)
{
    __shared__ __align__(16) float sm[4 * WSM];   // 47.1 KB static

    const int tid  = threadIdx.x;
    const int warp = tid >> 5;
    const int lane = tid & 31;
    const int wb0  = blockIdx.x * GB + warp * WG;  // warp's first batch
    const int g    = lane >> 1;                    // batch within warp
    const int s    = lane & 1;                     // pair sub-thread
    const size_t gb = (size_t)(wb0 + g);

    float* wsm = sm + warp * WSM;
    float* sF = wsm;                 // WG*68 = 1088  (P_new out)
    float* sP = wsm + 1088;          // 1088  (scratch A|S|XP|y after P dead)
    float* sH = wsm + 2176;          // WG*36 = 576   (K out)
    float* sx = wsm + 2752;          // WG*12 = 192   (x_new out)

    // ---- direct per-thread loads, issued first for MLP ----
    float4 r4a = *reinterpret_cast<const float4*>(gR + gb * 16 + (2*s) * 4);
    float4 r4b = *reinterpret_cast<const float4*>(gR + gb * 16 + (2*s + 1) * 4);
    float z2a = gz[gb * 4 + 2*s];
    float z2b = gz[gb * 4 + 2*s + 1];
    float xv[8];
    ld_row8(xv, gx + gb * 8);
    float pp[4][8];                  // init with own Q rows
#pragma unroll
    for (int i = 0; i < 4; ++i)
        ld_row8(pp[i], gQ + gb * 64 + (s + 2*i) * 8);

    // ---- warp-local staging (coalesced) ----
    stage_in_w<64, SF>(sF, gF, wb0, lane);
    stage_in_w<64, SF>(sP, gP, wb0, lane);
    stage_in_w<32, SH>(sH, gH, wb0, lane);
    __syncwarp();

    float* Fb = sF + g * SF;
    float* Pb = sP + g * SF;
    float* Hb = sH + g * SH;
    float* xb = sx + g * SX;
    float* Ab  = Pb;                 // A [8][4] after P dead
    float* Sb  = Pb + 36;            // S [4][4]
    float* XPb = Pb + 52;            // x_pred [8]
    float* Yb  = Pb + 60;            // y [4]

    // ---- own F rows; x_pred own rows ----
    float f[4][8];
#pragma unroll
    for (int i = 0; i < 4; ++i) ld_row8(f[i], Fb + (s + 2*i) * 8);
    float xp[4];
#pragma unroll
    for (int i = 0; i < 4; ++i) {
        float u = 0.f;
#pragma unroll
        for (int j = 0; j < 8; ++j) u += f[i][j] * xv[j];
        xp[i] = u;
    }

    // ---- T rows: T[r][:] = sum_k F[r][k] * P[k][:] ----
    float t[4][8];
#pragma unroll
    for (int i = 0; i < 4; ++i)
#pragma unroll
        for (int j = 0; j < 8; ++j) t[i][j] = 0.f;
#pragma unroll
    for (int k = 0; k < 8; ++k) {
        float pr[8];
        ld_row8(pr, Pb + k * 8);
#pragma unroll
        for (int i = 0; i < 4; ++i) {
            float fk = f[i][k];
#pragma unroll
            for (int j = 0; j < 8; ++j) t[i][j] += fk * pr[j];
        }
    }

    // ---- P_pred rows: pp[i][j] += T[i] . F[j][:] ----
#pragma unroll
    for (int j = 0; j < 8; ++j) {
        float fr[8];
        ld_row8(fr, Fb + j * 8);
#pragma unroll
        for (int i = 0; i < 4; ++i) {
            float u = pp[i][j];
#pragma unroll
            for (int k = 0; k < 8; ++k) u += t[i][k] * fr[k];
            pp[i][j] = u;
        }
    }

    // ---- A rows: A[r][m] = pp[r] . H[m] ----
    float a[4][4];
#pragma unroll
    for (int m = 0; m < 4; ++m) {
        float hr[8];
        ld_row8(hr, Hb + m * 8);
#pragma unroll
        for (int i = 0; i < 4; ++i) {
            float u = 0.f;
#pragma unroll
            for (int j = 0; j < 8; ++j) u += pp[i][j] * hr[j];
            a[i][m] = u;
        }
    }

    // ---- publish A (overlay dead P) + x_pred ----
    __syncwarp();                    // pair done reading Pb
#pragma unroll
    for (int i = 0; i < 4; ++i)
        *reinterpret_cast<float4*>(Ab + (s + 2*i) * 4) =
            make_float4(a[i][0], a[i][1], a[i][2], a[i][3]);
#pragma unroll
    for (int i = 0; i < 4; ++i) XPb[s + 2*i] = xp[i];
    __syncwarp();                    // publish

    // ---- gather full A into regs (reused for S and P_new) ----
    float af[32];
#pragma unroll
    for (int r = 0; r < 8; ++r) {
        float4 ar = *reinterpret_cast<const float4*>(Ab + r * 4);
        af[r*4+0]=ar.x; af[r*4+1]=ar.y; af[r*4+2]=ar.z; af[r*4+3]=ar.w;
    }
    float xpv[8];
    ld_row8(xpv, XPb);

    // ---- S rows {2s, 2s+1}; y rows {2s, 2s+1} ----
#pragma unroll
    for (int mi = 0; mi < 2; ++mi) {
        int m = 2*s + mi;
        float hm[8];
        ld_row8(hm, Hb + m * 8);
        float4 rr = (mi == 0) ? r4a : r4b;
        float c0 = rr.x, c1 = rr.y, c2 = rr.z, c3 = rr.w;
        if (m == 0) c0 += EPS; else if (m == 1) c1 += EPS;
        else if (m == 2) c2 += EPS; else c3 += EPS;
        float yacc = (mi == 0) ? z2a : z2b;
#pragma unroll
        for (int i = 0; i < 8; ++i) {
            float hi = hm[i];
            c0 += hi * af[i*4+0]; c1 += hi * af[i*4+1];
            c2 += hi * af[i*4+2]; c3 += hi * af[i*4+3];
            yacc -= hi * xpv[i];
        }
        *reinterpret_cast<float4*>(Sb + m * 4) = make_float4(c0, c1, c2, c3);
        Yb[m] = yacc;
    }
    __syncwarp();                    // publish S + y; last Hb read complete

    // ---- Cholesky of S (redundant per thread) ----
    float4 S0 = *reinterpret_cast<const float4*>(Sb);
    float4 S1 = *reinterpret_cast<const float4*>(Sb + 4);
    float4 S2 = *reinterpret_cast<const float4*>(Sb + 8);
    float4 S3 = *reinterpret_cast<const float4*>(Sb + 12);
    float4 yv = *reinterpret_cast<const float4*>(Yb);
    float y[4] = {yv.x, yv.y, yv.z, yv.w};

    float iL00 = rsqrtf(S0.x);
    float L10 = S1.x * iL00, L20 = S2.x * iL00, L30 = S3.x * iL00;
    float iL11 = rsqrtf(S1.y - L10*L10);
    float L21 = (S2.y - L20*L10) * iL11;
    float L31 = (S3.y - L30*L10) * iL11;
    float iL22 = rsqrtf(S2.z - L20*L20 - L21*L21);
    float L32 = (S3.z - L30*L20 - L31*L21) * iL22;
    float iL33 = rsqrtf(S3.w - L30*L30 - L31*L31 - L32*L32);

    // ---- K rows (own): solve; x_new; P_new; write to smem out regions ----
#pragma unroll
    for (int i = 0; i < 4; ++i) {
        float w0 = a[i][0] * iL00;
        float w1 = (a[i][1] - L10*w0) * iL11;
        float w2 = (a[i][2] - L20*w0 - L21*w1) * iL22;
        float w3 = (a[i][3] - L30*w0 - L31*w1 - L32*w2) * iL33;
        float k3 = w3 * iL33;
        float k2 = (w2 - L32*k3) * iL22;
        float k1 = (w1 - L21*k2 - L31*k3) * iL11;
        float k0 = (w0 - L10*k1 - L20*k2 - L30*k3) * iL00;

        float xn = xp[i] + k0*y[0] + k1*y[1] + k2*y[2] + k3*y[3];

        float pn[8];
#pragma unroll
        for (int j = 0; j < 8; ++j)
            pn[j] = pp[i][j] - (k0*af[j*4+0] + k1*af[j*4+1] +
                                k2*af[j*4+2] + k3*af[j*4+3]);

        st_row8(Fb + (s + 2*i) * 8, pn);                         // P_new -> sF
        *reinterpret_cast<float4*>(Hb + (s + 2*i) * 4) =
            make_float4(k0, k1, k2, k3);                         // K -> sH
        xb[s + 2*i] = xn;                                        // x_new -> sx
    }

    __syncwarp();                    // warp-local drain
    stage_out_w<8, SX>(out, sx, wb0, lane);
    stage_out_w<64, SF>(out + (size_t)8 * BT, sF, wb0, lane);
    stage_out_w<32, SH>(out + (size_t)72 * BT, sH, wb0, lane);
}

extern "C" void kernel_launch(void* const* d_in, const int* in_sizes, int n_in,
                              void* d_out, int out_size) {
    const float* x_est = (const float*)d_in[0];
    const float* P_est = (const float*)d_in[1];
    const float* F     = (const float*)d_in[2];
    const float* Q     = (const float*)d_in[3];
    const float* z     = (const float*)d_in[4];
    const float* H     = (const float*)d_in[5];
    const float* R     = (const float*)d_in[6];
    float* out = (float*)d_out;

    kf_kernel<<<BT / GB, TPB>>>(x_est, P_est, F, Q, z, H, R, out);
}

// round 10
// speedup vs baseline: 1.1370x; 1.1370x over previous
#include <cuda_runtime.h>
#include <cstdint>

// Batched Kalman filter: B=262144, N=8, M=4, fp32.
// Warp-autonomous, 4 threads/batch (lane&3 = s owns rows {s, s+4}), 8 batches
// per warp. F/P/H staged via cp.async into padded smem; Q/R/z/x loaded direct
// (sector-clean). HP = A^T symmetry. Outputs: x_new[B,8], P_new[B,8,8], K[B,8,4].

constexpr int BT  = 262144;
constexpr int TPB = 128;          // 4 warps
constexpr int WG  = 8;            // batches per warp
constexpr int GB  = 32;           // batches per block
constexpr float EPS = 1e-6f;

constexpr int SF = 68;            // padded stride for 64-float mats
constexpr int SH = 36;            // 32-float mats
constexpr int SX = 12;            // 8-float out vec
constexpr int WSM = WG*SF*2 + WG*SH + WG*SX;   // 1472 floats / warp

__device__ __forceinline__ uint32_t smem_u32(const void* p) {
    return (uint32_t)__cvta_generic_to_shared(p);
}

template<int E, int S>
__device__ __forceinline__ void stage_in_async(float* smp, const float* __restrict__ gp,
                                               int wb0, int lane) {
    const float* gsrc = gp + (size_t)wb0 * E;
    constexpr int T4 = WG * E / 4;
#pragma unroll
    for (int i = lane; i < T4; i += 32) {
        int e = i * 4;
        uint32_t dst = smem_u32(smp + (e / E) * S + (e % E));
        const float* src = gsrc + e;
        asm volatile("cp.async.ca.shared.global [%0], [%1], 16;"
                     :: "r"(dst), "l"(src));
    }
}

template<int E, int S>
__device__ __forceinline__ void stage_out_w(float* __restrict__ gp, const float* smp,
                                            int wb0, int lane) {
    float4* g4 = reinterpret_cast<float4*>(gp + (size_t)wb0 * E);
    constexpr int T4 = WG * E / 4;
#pragma unroll
    for (int i = lane; i < T4; i += 32) {
        int e = i * 4;
        g4[i] = *reinterpret_cast<const float4*>(smp + (e / E) * S + (e % E));
    }
}

__device__ __forceinline__ void ld_row8(float* d, const float* s) {
    float4 a = *reinterpret_cast<const float4*>(s);
    float4 b = *reinterpret_cast<const float4*>(s + 4);
    d[0]=a.x; d[1]=a.y; d[2]=a.z; d[3]=a.w;
    d[4]=b.x; d[5]=b.y; d[6]=b.z; d[7]=b.w;
}
__device__ __forceinline__ void st_row8(float* d, const float* s) {
    *reinterpret_cast<float4*>(d)     = make_float4(s[0], s[1], s[2], s[3]);
    *reinterpret_cast<float4*>(d + 4) = make_float4(s[4], s[5], s[6], s[7]);
}

__global__ __launch_bounds__(TPB, 5) void kf_kernel(
    const float* __restrict__ gx, const float* __restrict__ gP,
    const float* __restrict__ gF, const float* __restrict__ gQ,
    const float* __restrict__ gz, const float* __restrict__ gH,
    const float* __restrict__ gR, float* __restrict__ out)
{
    __shared__ __align__(16) float sm[4 * WSM];   // 23.6 KB

    const int tid  = threadIdx.x;
    const int warp = tid >> 5;
    const int lane = tid & 31;
    const int wb0  = blockIdx.x * GB + warp * WG;
    const int g    = lane >> 2;          // batch within warp (0..7)
    const int s    = lane & 3;           // sub-thread; owns rows s, s+4
    const int r0   = s, r1 = s + 4;
    const size_t gb = (size_t)(wb0 + g);

    float* wsm = sm + warp * WSM;
    float* sF = wsm;                  // WG*68 = 544  (P_new out)
    float* sP = wsm + 544;            // 544  (scratch A|S|XP|y after P dead)
    float* sH = wsm + 1088;           // WG*36 = 288  (K out)
    float* sx = wsm + 1376;           // WG*12 = 96   (x_new out)

    // ---- direct loads first (in flight across the cp.async wait) ----
    float4 rr = *reinterpret_cast<const float4*>(gR + gb * 16 + s * 4);
    float zs  = gz[gb * 4 + s];
    float q0[8], q1[8];
    ld_row8(q0, gQ + gb * 64 + r0 * 8);
    ld_row8(q1, gQ + gb * 64 + r1 * 8);
    float xv[8];
    ld_row8(xv, gx + gb * 8);

    // ---- async staging of F, P, H ----
    stage_in_async<64, SF>(sF, gF, wb0, lane);
    stage_in_async<64, SF>(sP, gP, wb0, lane);
    stage_in_async<32, SH>(sH, gH, wb0, lane);
    asm volatile("cp.async.commit_group;");
    asm volatile("cp.async.wait_group 0;");
    __syncwarp();

    float* Fb = sF + g * SF;
    float* Pb = sP + g * SF;
    float* Hb = sH + g * SH;
    float* xb = sx + g * SX;
    float* Ab  = Pb;                  // A [8][4] (row r at +4r) after P dead
    float* Sb  = Pb + 36;             // S [4][4]
    float* XPb = Pb + 52;             // x_pred [8]
    float* Yb  = Pb + 60;             // y [4]

    // ---- own F rows; x_pred ----
    float f0[8], f1[8];
    ld_row8(f0, Fb + r0 * 8);
    ld_row8(f1, Fb + r1 * 8);
    float xp0 = 0.f, xp1 = 0.f;
#pragma unroll
    for (int j = 0; j < 8; ++j) { xp0 += f0[j]*xv[j]; xp1 += f1[j]*xv[j]; }

    // ---- T rows: T[r][:] = sum_k F[r][k] * P[k][:] ----
    float t0[8], t1[8];
#pragma unroll
    for (int j = 0; j < 8; ++j) { t0[j] = 0.f; t1[j] = 0.f; }
#pragma unroll
    for (int k = 0; k < 8; ++k) {
        float pr[8];
        ld_row8(pr, Pb + k * 8);
        float fk0 = f0[k], fk1 = f1[k];
#pragma unroll
        for (int j = 0; j < 8; ++j) { t0[j] += fk0 * pr[j]; t1[j] += fk1 * pr[j]; }
    }

    // ---- P_pred rows: pp[r][j] = Q[r][j] + T[r] . F[j] ----
    float pp0[8], pp1[8];
#pragma unroll
    for (int j = 0; j < 8; ++j) {
        float fr[8];
        ld_row8(fr, Fb + j * 8);
        float u0 = q0[j], u1 = q1[j];
#pragma unroll
        for (int k = 0; k < 8; ++k) { u0 += t0[k]*fr[k]; u1 += t1[k]*fr[k]; }
        pp0[j] = u0; pp1[j] = u1;
    }

    // ---- A rows: A[r][m] = pp[r] . H[m] ----
    float a0[4], a1[4];
#pragma unroll
    for (int m = 0; m < 4; ++m) {
        float hr[8];
        ld_row8(hr, Hb + m * 8);
        float u0 = 0.f, u1 = 0.f;
#pragma unroll
        for (int j = 0; j < 8; ++j) { u0 += pp0[j]*hr[j]; u1 += pp1[j]*hr[j]; }
        a0[m] = u0; a1[m] = u1;
    }

    // ---- publish A (overlay dead P) + x_pred ----
    __syncwarp();                     // quad done reading Pb
    *reinterpret_cast<float4*>(Ab + r0 * 4) = make_float4(a0[0], a0[1], a0[2], a0[3]);
    *reinterpret_cast<float4*>(Ab + r1 * 4) = make_float4(a1[0], a1[1], a1[2], a1[3]);
    XPb[r0] = xp0; XPb[r1] = xp1;
    __syncwarp();                     // publish

    // ---- S row s = R[s] + eps*e_s + sum_i H[s][i]*A[i][:]; y[s] ----
    float hs[8];
    ld_row8(hs, Hb + s * 8);
    {
        float c0 = rr.x, c1 = rr.y, c2 = rr.z, c3 = rr.w;
        if (s == 0) c0 += EPS; else if (s == 1) c1 += EPS;
        else if (s == 2) c2 += EPS; else c3 += EPS;
        float xpv[8];
        ld_row8(xpv, XPb);
        float yacc = zs;
#pragma unroll
        for (int i = 0; i < 8; ++i) {
            float4 ar = *reinterpret_cast<const float4*>(Ab + i * 4);
            float hi = hs[i];
            c0 += hi * ar.x; c1 += hi * ar.y;
            c2 += hi * ar.z; c3 += hi * ar.w;
            yacc -= hi * xpv[i];
        }
        *reinterpret_cast<float4*>(Sb + s * 4) = make_float4(c0, c1, c2, c3);
        Yb[s] = yacc;
    }
    __syncwarp();                     // publish S + y; last Hb reads complete

    // ---- Cholesky of S (redundant per thread) ----
    float4 S0 = *reinterpret_cast<const float4*>(Sb);
    float4 S1 = *reinterpret_cast<const float4*>(Sb + 4);
    float4 S2 = *reinterpret_cast<const float4*>(Sb + 8);
    float4 S3 = *reinterpret_cast<const float4*>(Sb + 12);
    float4 yv = *reinterpret_cast<const float4*>(Yb);
    float y[4] = {yv.x, yv.y, yv.z, yv.w};

    float iL00 = rsqrtf(S0.x);
    float L10 = S1.x * iL00, L20 = S2.x * iL00, L30 = S3.x * iL00;
    float iL11 = rsqrtf(S1.y - L10*L10);
    float L21 = (S2.y - L20*L10) * iL11;
    float L31 = (S3.y - L30*L10) * iL11;
    float iL22 = rsqrtf(S2.z - L20*L20 - L21*L21);
    float L32 = (S3.z - L30*L20 - L31*L21) * iL22;
    float iL33 = rsqrtf(S3.w - L30*L30 - L31*L31 - L32*L32);

    // ---- K rows (own): solve S k = a ----
    float k0[4], k1[4];
    {
        float w0 = a0[0] * iL00;
        float w1 = (a0[1] - L10*w0) * iL11;
        float w2 = (a0[2] - L20*w0 - L21*w1) * iL22;
        float w3 = (a0[3] - L30*w0 - L31*w1 - L32*w2) * iL33;
        k0[3] = w3 * iL33;
        k0[2] = (w2 - L32*k0[3]) * iL22;
        k0[1] = (w1 - L21*k0[2] - L31*k0[3]) * iL11;
        k0[0] = (w0 - L10*k0[1] - L20*k0[2] - L30*k0[3]) * iL00;
    }
    {
        float w0 = a1[0] * iL00;
        float w1 = (a1[1] - L10*w0) * iL11;
        float w2 = (a1[2] - L20*w0 - L21*w1) * iL22;
        float w3 = (a1[3] - L30*w0 - L31*w1 - L32*w2) * iL33;
        k1[3] = w3 * iL33;
        k1[2] = (w2 - L32*k1[3]) * iL22;
        k1[1] = (w1 - L21*k1[2] - L31*k1[3]) * iL11;
        k1[0] = (w0 - L10*k1[1] - L20*k1[2] - L30*k1[3]) * iL00;
    }

    // ---- x_new own rows ----
    float xn0 = xp0, xn1 = xp1;
#pragma unroll
    for (int m = 0; m < 4; ++m) { xn0 += k0[m]*y[m]; xn1 += k1[m]*y[m]; }

    // ---- P_new rows: pn[r][j] = pp[r][j] - K[r] . A[j]   (HP = A^T) ----
    float pn0[8], pn1[8];
#pragma unroll
    for (int j = 0; j < 8; ++j) {
        float4 ar = *reinterpret_cast<const float4*>(Ab + j * 4);
        pn0[j] = pp0[j] - (k0[0]*ar.x + k0[1]*ar.y + k0[2]*ar.z + k0[3]*ar.w);
        pn1[j] = pp1[j] - (k1[0]*ar.x + k1[1]*ar.y + k1[2]*ar.z + k1[3]*ar.w);
    }

    // ---- stores: P_new -> sF (F dead), K -> sH (H reads fenced above), x_new -> sx
    st_row8(Fb + r0 * 8, pn0);
    st_row8(Fb + r1 * 8, pn1);
    *reinterpret_cast<float4*>(Hb + r0 * 4) = make_float4(k0[0], k0[1], k0[2], k0[3]);
    *reinterpret_cast<float4*>(Hb + r1 * 4) = make_float4(k1[0], k1[1], k1[2], k1[3]);
    xb[r0] = xn0; xb[r1] = xn1;

    __syncwarp();                     // warp-local drain
    stage_out_w<8, SX>(out, sx, wb0, lane);
    stage_out_w<64, SF>(out + (size_t)8 * BT, sF, wb0, lane);
    stage_out_w<32, SH>(out + (size_t)72 * BT, sH, wb0, lane);
}

extern "C" void kernel_launch(void* const* d_in, const int* in_sizes, int n_in,
                              void* d_out, int out_size) {
    const float* x_est = (const float*)d_in[0];
    const float* P_est = (const float*)d_in[1];
    const float* F     = (const float*)d_in[2];
    const float* Q     = (const float*)d_in[3];
    const float* z     = (const float*)d_in[4];
    const float* H     = (const float*)d_in[5];
    const float* R     = (const float*)d_in[6];
    float* out = (float*)d_out;

    kf_kernel<<<BT / GB, TPB>>>(x_est, P_est, F, Q, z, H, R, out);
}